// round 7
// baseline (speedup 1.0000x reference)
#include <cuda_runtime.h>
#include <cuda_bf16.h>
#include <mma.h>
#include <cstdint>

using namespace nvcuda;

#define TT 128
#define BB 256
#define DG 512
#define DH 1024
#define LN_EPS 1e-5f

#define BM 64
#define BN 128
#define BK 32
#define APITCH 40                 // smem row pitch in bf16 elements (80 B)
#define NSPLIT 4
#define KS (DH / NSPLIT)          // 256

// ---------------------------------------------------------------------------
// Device scratch (referenced ONLY from device code — never passed from host)
// ---------------------------------------------------------------------------
__device__ __align__(256) __nv_bfloat16 g_zhi[TT * BB * DG];
__device__ __align__(256) __nv_bfloat16 g_zlo[TT * BB * DG];
__device__ __align__(256) __nv_bfloat16 g_whh_hi[DH * DH];
__device__ __align__(256) __nv_bfloat16 g_whh_lo[DH * DH];
__device__ __align__(256) __nv_bfloat16 g_wg_hi[DH * DG];
__device__ __align__(256) __nv_bfloat16 g_wg_lo[DH * DG];
__device__ __align__(256) __nv_bfloat16 g_hhi[BB * DH];
__device__ __align__(256) __nv_bfloat16 g_hlo[BB * DH];
__device__ __align__(256) float g_partials[NSPLIT * BB * DH];
__device__ int g_flag_gemm[128];
__device__ int g_flag_ln[128];

// ---------------------------------------------------------------------------
// PTX helpers (family-portable: sm_70+/sm_80+)
// ---------------------------------------------------------------------------
__device__ __forceinline__ void cp16(uint32_t s, const void* g) {
    asm volatile("cp.async.cg.shared.global [%0], [%1], 16;" :: "r"(s), "l"(g));
}
__device__ __forceinline__ void cp_commit() {
    asm volatile("cp.async.commit_group;" ::: "memory");
}
template<int N>
__device__ __forceinline__ void cp_wait() {
    asm volatile("cp.async.wait_group %0;" :: "n"(N) : "memory");
}
__device__ __forceinline__ void st_release(int* p, int v) {
    asm volatile("st.global.release.gpu.b32 [%0], %1;" :: "l"(p), "r"(v) : "memory");
}
__device__ __forceinline__ int ld_acquire(const int* p) {
    int v;
    asm volatile("ld.global.acquire.gpu.b32 %0, [%1];" : "=r"(v) : "l"(p) : "memory");
    return v;
}
// Wait until flags[base + lane] >= tval for all 32 lanes of the group.
__device__ __forceinline__ void group_wait(int* flags, int base, int tval) {
    if (threadIdx.x < 32) {
        int* p = flags + base + threadIdx.x;
        while (ld_acquire(p) < tval) { __nanosleep(50); }
    }
    __syncthreads();
}

// ---------------------------------------------------------------------------
// fp32 -> bf16 hi/lo split kernels. TARGET: 0=z, 1=W_h, 2=W_g
// ---------------------------------------------------------------------------
template<int TARGET>
__global__ __launch_bounds__(256) void split_kernel(const float* __restrict__ src, int n4) {
    int i = blockIdx.x * 256 + threadIdx.x;
    if (i >= n4) return;
    __nv_bfloat16* hi;
    __nv_bfloat16* lo;
    if (TARGET == 0) { hi = g_zhi;    lo = g_zlo; }
    if (TARGET == 1) { hi = g_whh_hi; lo = g_whh_lo; }
    if (TARGET == 2) { hi = g_wg_hi;  lo = g_wg_lo; }
    float4 v = ((const float4*)src)[i];
    __nv_bfloat16 h0 = __float2bfloat16(v.x);
    __nv_bfloat16 h1 = __float2bfloat16(v.y);
    __nv_bfloat16 h2 = __float2bfloat16(v.z);
    __nv_bfloat16 h3 = __float2bfloat16(v.w);
    __nv_bfloat162 p;
    p.x = h0; p.y = h1; ((__nv_bfloat162*)hi)[i * 2]     = p;
    p.x = h2; p.y = h3; ((__nv_bfloat162*)hi)[i * 2 + 1] = p;
    p.x = __float2bfloat16(v.x - __bfloat162float(h0));
    p.y = __float2bfloat16(v.y - __bfloat162float(h1));
    ((__nv_bfloat162*)lo)[i * 2] = p;
    p.x = __float2bfloat16(v.z - __bfloat162float(h2));
    p.y = __float2bfloat16(v.w - __bfloat162float(h3));
    ((__nv_bfloat162*)lo)[i * 2 + 1] = p;
}

__global__ void init_flags() {
    int i = threadIdx.x;
    if (i < 128) { g_flag_gemm[i] = 0; g_flag_ln[i] = 0; }
}

// ---------------------------------------------------------------------------
// SMEM layout for the GEMM stages (shared by both GEMM kernels)
// ---------------------------------------------------------------------------
#define SA_HI 0
#define SA_LO 5120
#define SB_HI 10240
#define SB_LO 20480
#define STAGE 30720
#define SMEMB (2 * STAGE)

// ---------------------------------------------------------------------------
// Standalone emulated-fp32 GEMM (zg projection):
//   out[M,N] = z[M,K] @ W_g[N,K]^T   (3 bf16 products hh+hl+lh)
// CTA tile 64x128, 8 warps (2m x 4n), warp tile 32x32, BK=32, dbl-buffered.
// ---------------------------------------------------------------------------
__global__ __launch_bounds__(256) void zg_gemm(float* __restrict__ Cout)
{
    extern __shared__ char smem[];
    const uint32_t sb = (uint32_t)__cvta_generic_to_shared(smem);
    const int tid = threadIdx.x;
    const int wid = tid >> 5;
    const int wm = wid & 1;
    const int wn = wid >> 1;
    const int n0 = blockIdx.x * BN;
    const int m0 = blockIdx.y * BM;
    constexpr int K = DG;
    constexpr int NIT = DG / BK;

    const __nv_bfloat16* __restrict__ Ahi = g_zhi;
    const __nv_bfloat16* __restrict__ Alo = g_zlo;
    const __nv_bfloat16* __restrict__ Bhi = g_wg_hi;
    const __nv_bfloat16* __restrict__ Blo = g_wg_lo;

    const int lr = tid >> 2;
    const int lc = tid & 3;

    wmma::fragment<wmma::accumulator, 16, 16, 16, float> acc[2][2];
    #pragma unroll
    for (int f = 0; f < 2; f++)
        #pragma unroll
        for (int n = 0; n < 2; n++)
            wmma::fill_fragment(acc[f][n], 0.0f);

    auto issue = [&](int it, int buf) {
        const int koff = it * BK;
        const uint32_t st = sb + buf * STAGE;
        const uint32_t rowoff = (uint32_t)(lr * 80 + lc * 16);
        const size_t ga = (size_t)(m0 + lr) * K + koff + lc * 8;
        cp16(st + SA_HI + rowoff, Ahi + ga);
        cp16(st + SA_LO + rowoff, Alo + ga);
        const size_t gb0 = (size_t)(n0 + lr) * K + koff + lc * 8;
        const size_t gb1 = (size_t)(n0 + lr + 64) * K + koff + lc * 8;
        const uint32_t rowoff1 = (uint32_t)((lr + 64) * 80 + lc * 16);
        cp16(st + SB_HI + rowoff,  Bhi + gb0);
        cp16(st + SB_LO + rowoff,  Blo + gb0);
        cp16(st + SB_HI + rowoff1, Bhi + gb1);
        cp16(st + SB_LO + rowoff1, Blo + gb1);
        cp_commit();
    };

    issue(0, 0);
    for (int kt = 0; kt < NIT; kt++) {
        if (kt + 1 < NIT) { issue(kt + 1, (kt + 1) & 1); cp_wait<1>(); }
        else              { cp_wait<0>(); }
        __syncthreads();
        const char* stc = smem + (size_t)(kt & 1) * STAGE;
        const __nv_bfloat16* sAh = (const __nv_bfloat16*)(stc + SA_HI);
        const __nv_bfloat16* sAl = (const __nv_bfloat16*)(stc + SA_LO);
        const __nv_bfloat16* sBh = (const __nv_bfloat16*)(stc + SB_HI);
        const __nv_bfloat16* sBl = (const __nv_bfloat16*)(stc + SB_LO);
        #pragma unroll
        for (int ks = 0; ks < 2; ks++) {
            wmma::fragment<wmma::matrix_a, 16, 16, 16, __nv_bfloat16, wmma::row_major> ah[2], al[2];
            wmma::fragment<wmma::matrix_b, 16, 16, 16, __nv_bfloat16, wmma::col_major> bh[2], bl[2];
            #pragma unroll
            for (int f = 0; f < 2; f++) {
                const int r = wm * 32 + f * 16;
                wmma::load_matrix_sync(ah[f], sAh + r * APITCH + ks * 16, APITCH);
                wmma::load_matrix_sync(al[f], sAl + r * APITCH + ks * 16, APITCH);
            }
            #pragma unroll
            for (int n = 0; n < 2; n++) {
                const int r = wn * 32 + n * 16;
                wmma::load_matrix_sync(bh[n], sBh + r * APITCH + ks * 16, APITCH);
                wmma::load_matrix_sync(bl[n], sBl + r * APITCH + ks * 16, APITCH);
            }
            #pragma unroll
            for (int f = 0; f < 2; f++)
                #pragma unroll
                for (int n = 0; n < 2; n++) {
                    wmma::mma_sync(acc[f][n], ah[f], bh[n], acc[f][n]);
                    wmma::mma_sync(acc[f][n], ah[f], bl[n], acc[f][n]);
                    wmma::mma_sync(acc[f][n], al[f], bh[n], acc[f][n]);
                }
        }
        __syncthreads();
    }

    #pragma unroll
    for (int f = 0; f < 2; f++) {
        const int row = m0 + wm * 32 + f * 16;
        #pragma unroll
        for (int n = 0; n < 2; n++) {
            const int col = n0 + wn * 32 + n * 16;
            wmma::store_matrix_sync(Cout + (size_t)row * DH + col, acc[f][n],
                                    DH, wmma::mem_row_major);
        }
    }
}

// ---------------------------------------------------------------------------
// LN row helper: full-CTA (256 threads) LayerNorm+ReLU of one row.
// v = per-thread 4 contiguous cols of the pre-activation. Writes h fp32 to
// dst_row and bf16 hi/lo splits to g_hhi/g_hlo.
// ---------------------------------------------------------------------------
__device__ __forceinline__ void ln_row(
    float4 v, float* dst, size_t base,
    const float* __restrict__ gamma, const float* __restrict__ beta,
    float* r1, float* r2)
{
    const int tid = threadIdx.x;
    const int wid = tid >> 5, lane = tid & 31;
    __syncthreads();   // protect r1/r2 reuse across consecutive calls
    float s1 = v.x + v.y + v.z + v.w;
    float s2 = v.x * v.x + v.y * v.y + v.z * v.z + v.w * v.w;
    #pragma unroll
    for (int o = 16; o > 0; o >>= 1) {
        s1 += __shfl_xor_sync(0xffffffffu, s1, o);
        s2 += __shfl_xor_sync(0xffffffffu, s2, o);
    }
    if (lane == 0) { r1[wid] = s1; r2[wid] = s2; }
    __syncthreads();
    if (wid == 0) {
        float a = (lane < 8) ? r1[lane] : 0.f;
        float b = (lane < 8) ? r2[lane] : 0.f;
        #pragma unroll
        for (int o = 4; o > 0; o >>= 1) {
            a += __shfl_xor_sync(0xffffffffu, a, o);
            b += __shfl_xor_sync(0xffffffffu, b, o);
        }
        if (lane == 0) { r1[0] = a; r2[0] = b; }
    }
    __syncthreads();
    const float mean = r1[0] * (1.0f / DH);
    const float var  = r2[0] * (1.0f / DH) - mean * mean;
    const float inv  = rsqrtf(var + LN_EPS);

    const float4 g = *(const float4*)(gamma + tid * 4);
    const float4 b = *(const float4*)(beta + tid * 4);
    float4 y;
    y.x = fmaxf((v.x - mean) * inv * g.x + b.x, 0.f);
    y.y = fmaxf((v.y - mean) * inv * g.y + b.y, 0.f);
    y.z = fmaxf((v.z - mean) * inv * g.z + b.z, 0.f);
    y.w = fmaxf((v.w - mean) * inv * g.w + b.w, 0.f);
    *(float4*)(dst + base) = y;

    __nv_bfloat16 h0 = __float2bfloat16(y.x);
    __nv_bfloat16 h1 = __float2bfloat16(y.y);
    __nv_bfloat16 h2 = __float2bfloat16(y.z);
    __nv_bfloat16 h3 = __float2bfloat16(y.w);
    __nv_bfloat162 p;
    p.x = h0; p.y = h1; *(__nv_bfloat162*)(g_hhi + base)     = p;
    p.x = h2; p.y = h3; *(__nv_bfloat162*)(g_hhi + base + 2) = p;
    p.x = __float2bfloat16(y.x - __bfloat162float(h0));
    p.y = __float2bfloat16(y.y - __bfloat162float(h1));
    *(__nv_bfloat162*)(g_hlo + base) = p;
    p.x = __float2bfloat16(y.z - __bfloat162float(h2));
    p.y = __float2bfloat16(y.w - __bfloat162float(h3));
    *(__nv_bfloat162*)(g_hlo + base + 2) = p;
}

// ---------------------------------------------------------------------------
// t=0 LN: pre = zg_0 + bias (h0 = 0). One CTA per row.
// ---------------------------------------------------------------------------
__global__ __launch_bounds__(256) void ln0_kernel(
    float* __restrict__ dst, const float* __restrict__ bias,
    const float* __restrict__ gamma, const float* __restrict__ beta)
{
    __shared__ float r1[8], r2[8];
    const int tid = threadIdx.x;
    const size_t base = (size_t)blockIdx.x * DH + tid * 4;
    float4 v = *(const float4*)(dst + base);
    float4 bb = *(const float4*)(bias + tid * 4);
    v.x += bb.x; v.y += bb.y; v.z += bb.z; v.w += bb.w;
    ln_row(v, dst, base, gamma, beta, r1, r2);
}

// ---------------------------------------------------------------------------
// Persistent recurrence kernel: 128 CTAs = 4 batch groups x 32 CTAs.
// Group g owns batch rows [g*64, g*64+64). Per step:
//   GEMM phase: CTA (ntile, z) computes the split-K partial
//               C[m-tile, n-tile] = h[m-rows, kslice] @ W_h[n-cols, kslice]^T
//   group flag barrier (release/acquire on 32 distinct addresses)
//   LN phase:   each CTA normalizes 2 rows (pre = zg_t + bias + 4 partials),
//               writes h and its bf16 hi/lo splits
//   group flag barrier -> next step's GEMM may read h.
// Groups are fully independent (recurrence is per-sample).
// ---------------------------------------------------------------------------
__global__ __launch_bounds__(256) void rnn_persistent(
    float* __restrict__ out, const float* __restrict__ bias,
    const float* __restrict__ gamma, const float* __restrict__ beta)
{
    extern __shared__ char smem[];
    __shared__ float r1[8], r2[8];
    const uint32_t sb = (uint32_t)__cvta_generic_to_shared(smem);
    const int tid = threadIdx.x;
    const int wid = tid >> 5;
    const int wm = wid & 1;
    const int wn = wid >> 1;
    const int c = blockIdx.x;          // 0..127
    const int grp = c >> 5;            // batch group 0..3
    const int idx = c & 31;
    const int ntile = idx & 7;
    const int z = idx >> 3;
    const int m0 = grp * 64;
    const int n0 = ntile * BN;
    const int kb = z * KS;
    constexpr int NIT = KS / BK;       // 8

    const int lr = tid >> 2;
    const int lc = tid & 3;

    for (int t = 1; t < TT; t++) {
        // h_{t-1} of this group must be fully written
        group_wait(g_flag_ln, grp * 32, t - 1);

        // ---- GEMM phase ----
        wmma::fragment<wmma::accumulator, 16, 16, 16, float> acc[2][2];
        #pragma unroll
        for (int f = 0; f < 2; f++)
            #pragma unroll
            for (int n = 0; n < 2; n++)
                wmma::fill_fragment(acc[f][n], 0.0f);

        auto issue = [&](int it, int buf) {
            const int koff = kb + it * BK;
            const uint32_t st = sb + buf * STAGE;
            const uint32_t rowoff = (uint32_t)(lr * 80 + lc * 16);
            const size_t ga = (size_t)(m0 + lr) * DH + koff + lc * 8;
            cp16(st + SA_HI + rowoff, g_hhi + ga);
            cp16(st + SA_LO + rowoff, g_hlo + ga);
            const size_t gb0 = (size_t)(n0 + lr) * DH + koff + lc * 8;
            const size_t gb1 = (size_t)(n0 + lr + 64) * DH + koff + lc * 8;
            const uint32_t rowoff1 = (uint32_t)((lr + 64) * 80 + lc * 16);
            cp16(st + SB_HI + rowoff,  g_whh_hi + gb0);
            cp16(st + SB_LO + rowoff,  g_whh_lo + gb0);
            cp16(st + SB_HI + rowoff1, g_whh_hi + gb1);
            cp16(st + SB_LO + rowoff1, g_whh_lo + gb1);
            cp_commit();
        };

        issue(0, 0);
        for (int kt = 0; kt < NIT; kt++) {
            if (kt + 1 < NIT) { issue(kt + 1, (kt + 1) & 1); cp_wait<1>(); }
            else              { cp_wait<0>(); }
            __syncthreads();
            const char* stc = smem + (size_t)(kt & 1) * STAGE;
            const __nv_bfloat16* sAh = (const __nv_bfloat16*)(stc + SA_HI);
            const __nv_bfloat16* sAl = (const __nv_bfloat16*)(stc + SA_LO);
            const __nv_bfloat16* sBh = (const __nv_bfloat16*)(stc + SB_HI);
            const __nv_bfloat16* sBl = (const __nv_bfloat16*)(stc + SB_LO);
            #pragma unroll
            for (int ks = 0; ks < 2; ks++) {
                wmma::fragment<wmma::matrix_a, 16, 16, 16, __nv_bfloat16, wmma::row_major> ah[2], al[2];
                wmma::fragment<wmma::matrix_b, 16, 16, 16, __nv_bfloat16, wmma::col_major> bh[2], bl[2];
                #pragma unroll
                for (int f = 0; f < 2; f++) {
                    const int r = wm * 32 + f * 16;
                    wmma::load_matrix_sync(ah[f], sAh + r * APITCH + ks * 16, APITCH);
                    wmma::load_matrix_sync(al[f], sAl + r * APITCH + ks * 16, APITCH);
                }
                #pragma unroll
                for (int n = 0; n < 2; n++) {
                    const int r = wn * 32 + n * 16;
                    wmma::load_matrix_sync(bh[n], sBh + r * APITCH + ks * 16, APITCH);
                    wmma::load_matrix_sync(bl[n], sBl + r * APITCH + ks * 16, APITCH);
                }
                #pragma unroll
                for (int f = 0; f < 2; f++)
                    #pragma unroll
                    for (int n = 0; n < 2; n++) {
                        wmma::mma_sync(acc[f][n], ah[f], bh[n], acc[f][n]);
                        wmma::mma_sync(acc[f][n], ah[f], bl[n], acc[f][n]);
                        wmma::mma_sync(acc[f][n], al[f], bh[n], acc[f][n]);
                    }
            }
            __syncthreads();
        }

        float* Cp = g_partials + (size_t)z * (BB * DH);
        #pragma unroll
        for (int f = 0; f < 2; f++) {
            const int row = m0 + wm * 32 + f * 16;
            #pragma unroll
            for (int n = 0; n < 2; n++) {
                const int col = n0 + wn * 32 + n * 16;
                wmma::store_matrix_sync(Cp + (size_t)row * DH + col, acc[f][n],
                                        DH, wmma::mem_row_major);
            }
        }
        __syncthreads();
        if (tid == 0) st_release(&g_flag_gemm[c], t);

        // all partials for this group's rows must be in
        group_wait(g_flag_gemm, grp * 32, t);

        // ---- LN phase: 2 rows per CTA ----
        float* zg = out + (size_t)t * BB * DH;
        #pragma unroll
        for (int rr = 0; rr < 2; rr++) {
            const int row = m0 + idx * 2 + rr;
            const size_t base = (size_t)row * DH + tid * 4;
            float4 v = *(const float4*)(zg + base);
            float4 bb = *(const float4*)(bias + tid * 4);
            v.x += bb.x; v.y += bb.y; v.z += bb.z; v.w += bb.w;
            #pragma unroll
            for (int s = 0; s < NSPLIT; s++) {
                float4 p = *(const float4*)(g_partials + (size_t)s * (BB * DH) + base);
                v.x += p.x; v.y += p.y; v.z += p.z; v.w += p.w;
            }
            ln_row(v, zg, base, gamma, beta, r1, r2);
        }
        __syncthreads();
        if (tid == 0) st_release(&g_flag_ln[c], t);
    }
}

// ---------------------------------------------------------------------------
// kernel_launch
// ---------------------------------------------------------------------------
extern "C" void kernel_launch(void* const* d_in, const int* in_sizes, int n_in,
                              void* d_out, int out_size)
{
    const float* z     = (const float*)d_in[0];   // [T,B,DG]
    const float* W_h   = (const float*)d_in[1];   // [DH,DH]
    const float* W_g   = (const float*)d_in[2];   // [DH,DG]
    const float* b_h   = (const float*)d_in[3];   // [DH]
    const float* gamma = (const float*)d_in[4];   // [DH]
    const float* beta  = (const float*)d_in[5];   // [DH]
    float* out = (float*)d_out;                   // [T,B,DH]

    cudaFuncSetAttribute(zg_gemm, cudaFuncAttributeMaxDynamicSharedMemorySize, SMEMB);
    cudaFuncSetAttribute(rnn_persistent, cudaFuncAttributeMaxDynamicSharedMemorySize, SMEMB);

    init_flags<<<1, 128>>>();

    // hi/lo bf16 splits
    split_kernel<0><<<(TT * BB * DG / 4 + 255) / 256, 256>>>(z, TT * BB * DG / 4);
    split_kernel<1><<<(DH * DH / 4 + 255) / 256, 256>>>(W_h, DH * DH / 4);
    split_kernel<2><<<(DH * DG / 4 + 255) / 256, 256>>>(W_g, DH * DG / 4);

    // zg(raw) = z @ W_g^T -> d_out  (M=32768, N=1024, K=512); bias added in LN
    zg_gemm<<<dim3(DH / BN, (TT * BB) / BM), 256, SMEMB>>>(out);

    // t = 0: pre = zg_0 + bias (h0 = 0)
    ln0_kernel<<<BB, 256>>>(out, b_h, gamma, beta);

    // t = 1..127: one persistent kernel, group-local flag barriers
    rnn_persistent<<<128, 256, SMEMB>>>(out, b_h, gamma, beta);
}